// round 3
// baseline (speedup 1.0000x reference)
#include <cuda_runtime.h>
#include <cuda_bf16.h>

#define NMAX 50000
#define EMAX 800000
#define KB 8          // branches
#define CI 32
#define CO 32
#define CM 36         // C_IN + 4

// scratch (device globals; allocation is forbidden)
__device__ float g_acc[NMAX * CO];     // per-node accumulated edge features
__device__ int   g_cnt[NMAX];          // per-node edge counts (in-degree)
__device__ int   g_bucket[KB * EMAX];  // edge ids grouped by branch
__device__ int   g_bcnt[KB];           // per-branch edge counts

// ---------------------------------------------------------------------------
// Kernel 0: zero the accumulators (must run every launch; harness re-times)
// ---------------------------------------------------------------------------
__global__ void k_zero(int n_acc, int n_cnt) {
    int i = blockIdx.x * blockDim.x + threadIdx.x;
    int stride = gridDim.x * blockDim.x;
    for (int j = i; j < n_acc; j += stride) g_acc[j] = 0.0f;
    for (int j = i; j < n_cnt; j += stride) g_cnt[j] = 0;
    if (i < KB) g_bcnt[i] = 0;
}

// ---------------------------------------------------------------------------
// Kernel 1: classify edges into 8 geometric branches (block-aggregated
// counting sort) + per-target degree counts
// ---------------------------------------------------------------------------
__global__ void __launch_bounds__(256) k_classify(
    const float* __restrict__ pos,
    const int* __restrict__ ei,
    int E)
{
    __shared__ int s_cnt[KB];
    __shared__ int s_base[KB];
    int t = threadIdx.x;
    if (t < KB) s_cnt[t] = 0;
    __syncthreads();

    int e = blockIdx.x * blockDim.x + t;
    int k = 0, r = 0;
    if (e < E) {
        int s = ei[e];
        int d = ei[E + e];
        float2 ps = reinterpret_cast<const float2*>(pos)[s];
        float2 pd = reinterpret_cast<const float2*>(pos)[d];
        float dx = ps.x - pd.x;
        float dy = ps.y - pd.y;
        k = (dx > 0.0f ? 1 : 0) + (dy > 0.0f ? 2 : 0)
          + ((fabsf(dx) - fabsf(dy)) > 0.0f ? 4 : 0);
        r = atomicAdd(&s_cnt[k], 1);
        atomicAdd(&g_cnt[d], 1);
    }
    __syncthreads();
    if (t < KB) s_base[t] = atomicAdd(&g_bcnt[t], s_cnt[t]);
    __syncthreads();
    if (e < E) g_bucket[k * EMAX + s_base[k] + r] = e;
}

// ---------------------------------------------------------------------------
// Kernel 2: per-edge 2-layer MLP (selected branch only), warp-per-edge,
// branch weights register-resident per warp. Scatter-add into g_acc.
// ---------------------------------------------------------------------------
__global__ void __launch_bounds__(128) k_edge_mlp(
    const float* __restrict__ x,
    const int*   __restrict__ ei,
    const float* __restrict__ ea,
    const float* __restrict__ ew,
    const float* __restrict__ W1,
    const float* __restrict__ b1,
    const float* __restrict__ W2,
    const float* __restrict__ b2,
    int E)
{
    const int k    = blockIdx.x & (KB - 1);     // branch for this block
    const int lane = threadIdx.x & 31;
    const int warp = threadIdx.x >> 5;
    const int wpb  = blockDim.x >> 5;
    const int wib  = (blockIdx.x >> 3) * wpb + warp;   // warp index within branch
    const int nw   = (gridDim.x >> 3) * wpb;           // warps per branch

    // Branch weights: lane c holds column c of W1 (36) and W2 (32).
    float w1[CM], w2[CO];
#pragma unroll
    for (int i = 0; i < CM; i++) w1[i] = W1[(k * CM + i) * CO + lane];
#pragma unroll
    for (int j = 0; j < CO; j++) w2[j] = W2[(k * CO + j) * CO + lane];
    const float b1c = b1[k * CO + lane];
    const float b2c = b2[k * CO + lane];

    const int cnt = g_bcnt[k];
    const int* __restrict__ bk = g_bucket + k * EMAX;

    for (int p = wib; p < cnt; p += nw) {
        const int e = bk[p];                  // broadcast load
        const int s = ei[e];
        const int d = ei[E + e];
        const float m  = x[s * CI + lane] - x[d * CI + lane];
        const float4 a4 = reinterpret_cast<const float4*>(ea)[e];
        const float w   = ew[e];

        // layer 1: h[c] = relu( sum_i m[i]*W1[i][c] + b1[c] ), 4 chains for ILP
        float h0 = 0.f, h1 = 0.f, h2 = 0.f, h3 = 0.f;
#pragma unroll
        for (int i = 0; i < CI; i += 4) {
            h0 = fmaf(__shfl_sync(0xffffffffu, m, i + 0), w1[i + 0], h0);
            h1 = fmaf(__shfl_sync(0xffffffffu, m, i + 1), w1[i + 1], h1);
            h2 = fmaf(__shfl_sync(0xffffffffu, m, i + 2), w1[i + 2], h2);
            h3 = fmaf(__shfl_sync(0xffffffffu, m, i + 3), w1[i + 3], h3);
        }
        h0 = fmaf(a4.x, w1[32], h0);
        h1 = fmaf(a4.y, w1[33], h1);
        h2 = fmaf(a4.z, w1[34], h2);
        h3 = fmaf(a4.w, w1[35], h3);
        const float h = fmaxf((h0 + h1) + (h2 + h3) + b1c, 0.0f);

        // layer 2: f[c] = relu( sum_j h[j]*W2[j][c] + b2[c] ) * ew
        float f0 = 0.f, f1 = 0.f, f2 = 0.f, f3 = 0.f;
#pragma unroll
        for (int j = 0; j < CO; j += 4) {
            f0 = fmaf(__shfl_sync(0xffffffffu, h, j + 0), w2[j + 0], f0);
            f1 = fmaf(__shfl_sync(0xffffffffu, h, j + 1), w2[j + 1], f1);
            f2 = fmaf(__shfl_sync(0xffffffffu, h, j + 2), w2[j + 2], f2);
            f3 = fmaf(__shfl_sync(0xffffffffu, h, j + 3), w2[j + 3], f3);
        }
        const float f = fmaxf((f0 + f1) + (f2 + f3) + b2c, 0.0f) * w;

        atomicAdd(&g_acc[d * CO + lane], f);
    }
}

// ---------------------------------------------------------------------------
// Kernel 3: out = acc/max(cnt,1) + x @ Wr + br   (warp per node)
// ---------------------------------------------------------------------------
__global__ void __launch_bounds__(128) k_finalize(
    const float* __restrict__ x,
    const float* __restrict__ Wr,
    const float* __restrict__ br,
    float* __restrict__ out,
    int N)
{
    const int lane = threadIdx.x & 31;
    const int warp = blockIdx.x * (blockDim.x >> 5) + (threadIdx.x >> 5);
    const int nw   = gridDim.x * (blockDim.x >> 5);

    float wr[CI];
#pragma unroll
    for (int i = 0; i < CI; i++) wr[i] = Wr[i * CO + lane];
    const float brc = br[lane];

    for (int n = warp; n < N; n += nw) {
        const float xv = x[n * CI + lane];
        float a0 = 0.f, a1 = 0.f, a2 = 0.f, a3 = 0.f;
#pragma unroll
        for (int i = 0; i < CI; i += 4) {
            a0 = fmaf(__shfl_sync(0xffffffffu, xv, i + 0), wr[i + 0], a0);
            a1 = fmaf(__shfl_sync(0xffffffffu, xv, i + 1), wr[i + 1], a1);
            a2 = fmaf(__shfl_sync(0xffffffffu, xv, i + 2), wr[i + 2], a2);
            a3 = fmaf(__shfl_sync(0xffffffffu, xv, i + 3), wr[i + 3], a3);
        }
        const float acc = g_acc[n * CO + lane];
        const float c   = (float)g_cnt[n];
        const float inv = 1.0f / fmaxf(c, 1.0f);
        out[n * CO + lane] = fmaf(acc, inv, (a0 + a1) + (a2 + a3) + brc);
    }
}

// ---------------------------------------------------------------------------
// Host launcher
// ---------------------------------------------------------------------------
extern "C" void kernel_launch(void* const* d_in, const int* in_sizes, int n_in,
                              void* d_out, int out_size)
{
    const float* x    = (const float*)d_in[0];   // [N, 32]
    const float* pos  = (const float*)d_in[1];   // [N, 2]
    const int*   ei   = (const int*)  d_in[2];   // [2, E]
    const float* ea   = (const float*)d_in[3];   // [E, 4]
    const float* ew   = (const float*)d_in[4];   // [E]
    const float* W1   = (const float*)d_in[5];   // [8, 36, 32]
    const float* b1   = (const float*)d_in[6];   // [8, 32]
    const float* W2   = (const float*)d_in[7];   // [8, 32, 32]
    const float* b2   = (const float*)d_in[8];   // [8, 32]
    const float* Wr   = (const float*)d_in[9];   // [32, 32]
    const float* br   = (const float*)d_in[10];  // [32]
    float* out = (float*)d_out;

    const int N = in_sizes[0] / CI;
    const int E = in_sizes[4];

    // 0) zero scratch
    k_zero<<<256, 1024>>>(N * CO, N);

    // 1) classify: counting sort of edges into 8 branches
    k_classify<<<(E + 255) / 256, 256>>>(pos, ei, E);

    // 2) per-edge MLP, warp-per-edge, branch-binned weights in registers
    //    grid = 8 branches * 256 blocks, 4 warps/block -> 1024 warps/branch
    k_edge_mlp<<<KB * 256, 128>>>(x, ei, ea, ew, W1, b1, W2, b2, E);

    // 3) mean + skip connection
    k_finalize<<<512, 128>>>(x, Wr, br, out, N);
}

// round 4
// speedup vs baseline: 1.2333x; 1.2333x over previous
#include <cuda_runtime.h>

#define NMAX 50000
#define EMAX 800000
#define KB 8          // branches
#define CI 32
#define CO 32
#define CM 36         // C_IN + 4

// scratch (device globals; allocation is forbidden)
__device__ float g_acc[NMAX * CO];          // per-node accumulated edge features
__device__ float g_skip[NMAX * CO];         // x @ Wr + br
__device__ float g_p[KB * NMAX * CO];       // per-branch x @ W1a  (51.2 MB)
__device__ int   g_cnt[NMAX];               // in-degree
__device__ int4  g_bucket[KB * EMAX];       // {e, src, dst, -} per branch (102 MB)
__device__ int   g_bcnt[KB];

// ---------------------------------------------------------------------------
// Kernel 0: zero accumulators / counters
// ---------------------------------------------------------------------------
__global__ void k_zero(int N) {
    int i = blockIdx.x * blockDim.x + threadIdx.x;
    int stride = gridDim.x * blockDim.x;
    float4* a4 = reinterpret_cast<float4*>(g_acc);
    const int n4 = N * CO / 4;
    for (int j = i; j < n4; j += stride) a4[j] = make_float4(0.f, 0.f, 0.f, 0.f);
    for (int j = i; j < N; j += stride) g_cnt[j] = 0;
    if (i < KB) g_bcnt[i] = 0;
}

// ---------------------------------------------------------------------------
// Kernel 1: classify edges into 8 branches (block-aggregated counting sort),
// emit packed {e, src, dst} records, count in-degree.
// ---------------------------------------------------------------------------
__global__ void __launch_bounds__(256) k_classify(
    const float* __restrict__ pos,
    const int* __restrict__ ei,
    int E)
{
    __shared__ int s_cnt[KB];
    __shared__ int s_base[KB];
    int t = threadIdx.x;
    if (t < KB) s_cnt[t] = 0;
    __syncthreads();

    int e = blockIdx.x * blockDim.x + t;
    int k = 0, r = 0, s = 0, d = 0;
    if (e < E) {
        s = ei[e];
        d = ei[E + e];
        float2 ps = reinterpret_cast<const float2*>(pos)[s];
        float2 pd = reinterpret_cast<const float2*>(pos)[d];
        float dx = ps.x - pd.x;
        float dy = ps.y - pd.y;
        k = (dx > 0.0f ? 1 : 0) + (dy > 0.0f ? 2 : 0)
          + ((fabsf(dx) - fabsf(dy)) > 0.0f ? 4 : 0);
        r = atomicAdd(&s_cnt[k], 1);
        atomicAdd(&g_cnt[d], 1);
    }
    __syncthreads();
    if (t < KB) s_base[t] = atomicAdd(&g_bcnt[t], s_cnt[t]);
    __syncthreads();
    if (e < E) g_bucket[k * EMAX + s_base[k] + r] = make_int4(e, s, d, 0);
}

// ---------------------------------------------------------------------------
// Kernel 2: precompute p[k] = x @ W1[k][0:32,:]  (k<8)  and  skip = x@Wr + br
// Thread-per-node, weights transposed in SMEM (broadcast LDS.128).
// ---------------------------------------------------------------------------
__global__ void __launch_bounds__(256) k_precompute(
    const float* __restrict__ x,
    const float* __restrict__ W1,
    const float* __restrict__ Wr,
    const float* __restrict__ br,
    int N)
{
    const int k = blockIdx.y;              // 0..7 = branches, 8 = skip
    __shared__ float4 s_w[CO * 8];         // s_w[c*8+ii] = W[4ii..4ii+3][c]
    __shared__ float  s_b[CO];

    const float* W = (k < KB) ? (W1 + k * CM * CO) : Wr;
    float* s_wf = reinterpret_cast<float*>(s_w);
    for (int t = threadIdx.x; t < CO * CI; t += blockDim.x) {
        int c = t >> 5, i = t & 31;
        s_wf[c * 32 + i] = W[i * CO + c];
    }
    for (int t = threadIdx.x; t < CO; t += blockDim.x)
        s_b[t] = (k == KB) ? br[t] : 0.0f;
    __syncthreads();

    const int n = blockIdx.x * blockDim.x + threadIdx.x;
    if (n >= N) return;

    float xr[CI];
    const float4* xv = reinterpret_cast<const float4*>(x) + n * 8;
#pragma unroll
    for (int ii = 0; ii < 8; ii++) {
        float4 v = xv[ii];
        xr[4 * ii + 0] = v.x; xr[4 * ii + 1] = v.y;
        xr[4 * ii + 2] = v.z; xr[4 * ii + 3] = v.w;
    }

    float4* outp = reinterpret_cast<float4*>(
        (k < KB) ? (g_p + (size_t)(k * N + n) * CO) : (g_skip + (size_t)n * CO));

    float o[4];
#pragma unroll
    for (int c = 0; c < CO; c++) {
        float acc = s_b[c];
#pragma unroll
        for (int ii = 0; ii < 8; ii++) {
            float4 w = s_w[c * 8 + ii];
            acc = fmaf(xr[4 * ii + 0], w.x, acc);
            acc = fmaf(xr[4 * ii + 1], w.y, acc);
            acc = fmaf(xr[4 * ii + 2], w.z, acc);
            acc = fmaf(xr[4 * ii + 3], w.w, acc);
        }
        o[c & 3] = acc;
        if ((c & 3) == 3)
            outp[c >> 2] = make_float4(o[0], o[1], o[2], o[3]);
    }
}

// ---------------------------------------------------------------------------
// Kernel 3: per-edge MLP, lane=edge, branch weights in SMEM (broadcast LDS),
// layer 1 mostly precomputed. Vector red scatter into g_acc.
// ---------------------------------------------------------------------------
__global__ void __launch_bounds__(256) k_edge_mlp(
    const float* __restrict__ ea,
    const float* __restrict__ ew,
    const float* __restrict__ W1,
    const float* __restrict__ b1,
    const float* __restrict__ W2,
    const float* __restrict__ b2,
    int N)
{
    const int k = blockIdx.y;
    __shared__ float4 s_w1b[CO];      // rows 32..35 of W1[k], per output c
    __shared__ float  s_b1[CO], s_b2[CO];
    __shared__ float4 s_w2[CO * 8];   // s_w2[c*8+jj] = W2[k][4jj..][c]

    for (int t = threadIdx.x; t < CO; t += blockDim.x) {
        s_w1b[t] = make_float4(W1[(k * CM + 32) * CO + t],
                               W1[(k * CM + 33) * CO + t],
                               W1[(k * CM + 34) * CO + t],
                               W1[(k * CM + 35) * CO + t]);
        s_b1[t] = b1[k * CO + t];
        s_b2[t] = b2[k * CO + t];
    }
    float* s_w2f = reinterpret_cast<float*>(s_w2);
    for (int t = threadIdx.x; t < CO * CO; t += blockDim.x) {
        int c = t >> 5, j = t & 31;
        s_w2f[c * 32 + j] = W2[(k * CO + j) * CO + c];
    }
    __syncthreads();

    const int cnt = g_bcnt[k];
    const int4* __restrict__ bk = g_bucket + k * EMAX;
    const float4* __restrict__ pbase =
        reinterpret_cast<const float4*>(g_p + (size_t)k * N * CO);

    const int stride = gridDim.x * blockDim.x;
    for (int i = blockIdx.x * blockDim.x + threadIdx.x; i < cnt; i += stride) {
        int4 esd = bk[i];
        const int e = esd.x, s = esd.y, d = esd.z;
        const float4 a4 = reinterpret_cast<const float4*>(ea)[e];
        const float w = ew[e];

        // gather precomputed rows, diff in place
        float h[CO];
        const float4* ps = pbase + s * 8;
        const float4* pd = pbase + d * 8;
#pragma unroll
        for (int ii = 0; ii < 8; ii++) {
            float4 a = ps[ii];
            float4 b = pd[ii];
            h[4 * ii + 0] = a.x - b.x;
            h[4 * ii + 1] = a.y - b.y;
            h[4 * ii + 2] = a.z - b.z;
            h[4 * ii + 3] = a.w - b.w;
        }

        // layer 1 remainder: + ea @ W1b + b1, relu
#pragma unroll
        for (int c = 0; c < CO; c++) {
            float4 wb = s_w1b[c];
            float t = h[c] + s_b1[c];
            t = fmaf(a4.x, wb.x, t);
            t = fmaf(a4.y, wb.y, t);
            t = fmaf(a4.z, wb.z, t);
            t = fmaf(a4.w, wb.w, t);
            h[c] = fmaxf(t, 0.0f);
        }

        // layer 2 + relu + edge weight, vector-red scatter
        float* dst = g_acc + (size_t)d * CO;
        float f4[4];
#pragma unroll
        for (int c = 0; c < CO; c++) {
            float acc = s_b2[c];
#pragma unroll
            for (int jj = 0; jj < 8; jj++) {
                float4 w2 = s_w2[c * 8 + jj];
                acc = fmaf(h[4 * jj + 0], w2.x, acc);
                acc = fmaf(h[4 * jj + 1], w2.y, acc);
                acc = fmaf(h[4 * jj + 2], w2.z, acc);
                acc = fmaf(h[4 * jj + 3], w2.w, acc);
            }
            f4[c & 3] = fmaxf(acc, 0.0f) * w;
            if ((c & 3) == 3) {
                asm volatile(
                    "red.global.add.v4.f32 [%0], {%1, %2, %3, %4};"
                    :: "l"(dst + c - 3),
                       "f"(f4[0]), "f"(f4[1]), "f"(f4[2]), "f"(f4[3])
                    : "memory");
            }
        }
    }
}

// ---------------------------------------------------------------------------
// Kernel 4: out = acc / max(cnt,1) + skip      (pure streaming, float4)
// ---------------------------------------------------------------------------
__global__ void __launch_bounds__(256) k_finalize(float* __restrict__ out, int N)
{
    const int i = blockIdx.x * blockDim.x + threadIdx.x;   // over N*8 float4s
    if (i >= N * 8) return;
    const int n = i >> 3;
    const float inv = 1.0f / fmaxf((float)g_cnt[n], 1.0f);
    const float4 a = reinterpret_cast<const float4*>(g_acc)[i];
    const float4 s = reinterpret_cast<const float4*>(g_skip)[i];
    float4 o;
    o.x = fmaf(a.x, inv, s.x);
    o.y = fmaf(a.y, inv, s.y);
    o.z = fmaf(a.z, inv, s.z);
    o.w = fmaf(a.w, inv, s.w);
    reinterpret_cast<float4*>(out)[i] = o;
}

// ---------------------------------------------------------------------------
// Host launcher
// ---------------------------------------------------------------------------
extern "C" void kernel_launch(void* const* d_in, const int* in_sizes, int n_in,
                              void* d_out, int out_size)
{
    const float* x    = (const float*)d_in[0];   // [N, 32]
    const float* pos  = (const float*)d_in[1];   // [N, 2]
    const int*   ei   = (const int*)  d_in[2];   // [2, E]
    const float* ea   = (const float*)d_in[3];   // [E, 4]
    const float* ew   = (const float*)d_in[4];   // [E]
    const float* W1   = (const float*)d_in[5];   // [8, 36, 32]
    const float* b1   = (const float*)d_in[6];   // [8, 32]
    const float* W2   = (const float*)d_in[7];   // [8, 32, 32]
    const float* b2   = (const float*)d_in[8];   // [8, 32]
    const float* Wr   = (const float*)d_in[9];   // [32, 32]
    const float* br   = (const float*)d_in[10];  // [32]
    float* out = (float*)d_out;

    const int N = in_sizes[0] / CI;
    const int E = in_sizes[4];

    // 0) zero scratch
    k_zero<<<256, 256>>>(N);

    // 1) classify: counting sort of edges into 8 branches, packed records
    k_classify<<<(E + 255) / 256, 256>>>(pos, ei, E);

    // 2) per-node precompute: p[k] = x @ W1a[k], skip = x @ Wr + br
    {
        dim3 grid((N + 255) / 256, KB + 1);
        k_precompute<<<grid, 256>>>(x, W1, Wr, br, N);
    }

    // 3) per-edge MLP (lane = edge), branch-specialized blocks
    {
        dim3 grid(64, KB);
        k_edge_mlp<<<grid, 256>>>(ea, ew, W1, b1, W2, b2, N);
    }

    // 4) mean + skip connection
    k_finalize<<<(N * 8 + 255) / 256, 256>>>(out, N);
}

// round 5
// speedup vs baseline: 1.5525x; 1.2588x over previous
#include <cuda_runtime.h>

#define NMAX 50000
#define EMAX 800000
#define KB 8          // branches
#define CI 32
#define CO 32
#define CM 36         // C_IN + 4

// scratch (device globals; allocation is forbidden)
__device__ float  g_acc[NMAX * CO];            // per-node accumulated edge features
__device__ float  g_skip[NMAX * CO];           // x @ Wr + br
__device__ float  g_p[KB * NMAX * CO];         // per-branch x @ W1a  (51.2 MB)
__device__ int    g_cnt[NMAX];                 // in-degree
__device__ float4 g_bucket[KB * EMAX * 2];     // 32B records {s,d,ea4,ew} (204 MB)
__device__ int    g_bcnt[KB];

// ---------------------------------------------------------------------------
// Kernel 0: zero accumulators / counters
// ---------------------------------------------------------------------------
__global__ void k_zero(int N) {
    int i = blockIdx.x * blockDim.x + threadIdx.x;
    int stride = gridDim.x * blockDim.x;
    float4* a4 = reinterpret_cast<float4*>(g_acc);
    const int n4 = N * CO / 4;
    for (int j = i; j < n4; j += stride) a4[j] = make_float4(0.f, 0.f, 0.f, 0.f);
    for (int j = i; j < N; j += stride) g_cnt[j] = 0;
    if (i < KB) g_bcnt[i] = 0;
}

// ---------------------------------------------------------------------------
// Kernel 1: classify edges into 8 branches (block-aggregated counting sort),
// emit packed 32B records {s, d, ea4, ew}, count in-degree.
// ---------------------------------------------------------------------------
__global__ void __launch_bounds__(256) k_classify(
    const float* __restrict__ pos,
    const int* __restrict__ ei,
    const float* __restrict__ ea,
    const float* __restrict__ ew,
    int E)
{
    __shared__ int s_cnt[KB];
    __shared__ int s_base[KB];
    int t = threadIdx.x;
    if (t < KB) s_cnt[t] = 0;
    __syncthreads();

    int e = blockIdx.x * blockDim.x + t;
    int k = 0, r = 0, s = 0, d = 0;
    float4 a4 = make_float4(0.f, 0.f, 0.f, 0.f);
    float w = 0.f;
    if (e < E) {
        s = ei[e];
        d = ei[E + e];
        a4 = reinterpret_cast<const float4*>(ea)[e];
        w = ew[e];
        float2 ps = reinterpret_cast<const float2*>(pos)[s];
        float2 pd = reinterpret_cast<const float2*>(pos)[d];
        float dx = ps.x - pd.x;
        float dy = ps.y - pd.y;
        k = (dx > 0.0f ? 1 : 0) + (dy > 0.0f ? 2 : 0)
          + ((fabsf(dx) - fabsf(dy)) > 0.0f ? 4 : 0);
        r = atomicAdd(&s_cnt[k], 1);
        atomicAdd(&g_cnt[d], 1);
    }
    __syncthreads();
    if (t < KB) s_base[t] = atomicAdd(&g_bcnt[t], s_cnt[t]);
    __syncthreads();
    if (e < E) {
        size_t p = (size_t)(k * EMAX + s_base[k] + r) * 2;
        g_bucket[p]     = make_float4(__int_as_float(s), __int_as_float(d), a4.x, a4.y);
        g_bucket[p + 1] = make_float4(a4.z, a4.w, w, 0.f);
    }
}

// ---------------------------------------------------------------------------
// Kernel 2: precompute p[k] = x @ W1[k][0:32,:]  (k<8)  and  skip = x@Wr + br
// ---------------------------------------------------------------------------
__global__ void __launch_bounds__(256) k_precompute(
    const float* __restrict__ x,
    const float* __restrict__ W1,
    const float* __restrict__ Wr,
    const float* __restrict__ br,
    int N)
{
    const int k = blockIdx.y;              // 0..7 = branches, 8 = skip
    __shared__ float4 s_w[CO * 8];         // s_w[c*8+ii] = W[4ii..4ii+3][c]
    __shared__ float  s_b[CO];

    const float* W = (k < KB) ? (W1 + k * CM * CO) : Wr;
    float* s_wf = reinterpret_cast<float*>(s_w);
    for (int t = threadIdx.x; t < CO * CI; t += blockDim.x) {
        int c = t >> 5, i = t & 31;
        s_wf[c * 32 + i] = W[i * CO + c];
    }
    for (int t = threadIdx.x; t < CO; t += blockDim.x)
        s_b[t] = (k == KB) ? br[t] : 0.0f;
    __syncthreads();

    const int n = blockIdx.x * blockDim.x + threadIdx.x;
    if (n >= N) return;

    float xr[CI];
    const float4* xv = reinterpret_cast<const float4*>(x) + n * 8;
#pragma unroll
    for (int ii = 0; ii < 8; ii++) {
        float4 v = xv[ii];
        xr[4 * ii + 0] = v.x; xr[4 * ii + 1] = v.y;
        xr[4 * ii + 2] = v.z; xr[4 * ii + 3] = v.w;
    }

    float4* outp = reinterpret_cast<float4*>(
        (k < KB) ? (g_p + (size_t)(k * N + n) * CO) : (g_skip + (size_t)n * CO));

    float o[4];
#pragma unroll
    for (int c = 0; c < CO; c++) {
        float acc = s_b[c];
#pragma unroll
        for (int ii = 0; ii < 8; ii++) {
            float4 w = s_w[c * 8 + ii];
            acc = fmaf(xr[4 * ii + 0], w.x, acc);
            acc = fmaf(xr[4 * ii + 1], w.y, acc);
            acc = fmaf(xr[4 * ii + 2], w.z, acc);
            acc = fmaf(xr[4 * ii + 3], w.w, acc);
        }
        o[c & 3] = acc;
        if ((c & 3) == 3)
            outp[c >> 2] = make_float4(o[0], o[1], o[2], o[3]);
    }
}

// ---------------------------------------------------------------------------
// Kernel 3: warp-tile edge MLP. Warp owns 32 edges; cooperative coalesced
// gather of p rows into SMEM tile; compute with lane = output channel so
// W1b/W2/b1/b2 live in registers; coalesced red scatter.
// ---------------------------------------------------------------------------
#define WPB 8   // warps per block
__global__ void __launch_bounds__(32 * WPB) k_edge_mlp(
    const float* __restrict__ W1,
    const float* __restrict__ b1,
    const float* __restrict__ W2,
    const float* __restrict__ b2,
    int N)
{
    const int k    = blockIdx.y;
    const int lane = threadIdx.x & 31;
    const int w    = threadIdx.x >> 5;

    __shared__ float s_tile[WPB][32][36];   // cols 0..31: m/h, 32..35: ea
    __shared__ int   s_d[WPB][32];
    __shared__ float s_ew[WPB][32];

    // lane = output channel c: register-resident weights
    float w2r[CO];
#pragma unroll
    for (int j = 0; j < CO; j++) w2r[j] = W2[(k * CO + j) * CO + lane];
    const float4 w1b = make_float4(W1[(k * CM + 32) * CO + lane],
                                   W1[(k * CM + 33) * CO + lane],
                                   W1[(k * CM + 34) * CO + lane],
                                   W1[(k * CM + 35) * CO + lane]);
    const float b1c = b1[k * CO + lane];
    const float b2c = b2[k * CO + lane];

    const int cnt = g_bcnt[k];
    const int ntile = (cnt + 31) >> 5;
    const float4* __restrict__ rec = g_bucket + (size_t)k * EMAX * 2;
    const float4* __restrict__ pb =
        reinterpret_cast<const float4*>(g_p + (size_t)k * N * CO);

    const int gwarp = blockIdx.x * WPB + w;
    const int nwarp = gridDim.x * WPB;

    for (int tile = gwarp; tile < ntile; tile += nwarp) {
        const int idx = (tile << 5) + lane;   // this lane's owned edge
        int si = 0, di = 0;
        float ewv = 0.f;
        float4 ea = make_float4(0.f, 0.f, 0.f, 0.f);
        if (idx < cnt) {
            float4 r0 = rec[(size_t)idx * 2];
            float4 r1 = rec[(size_t)idx * 2 + 1];
            si = __float_as_int(r0.x);
            di = __float_as_int(r0.y);
            ea = make_float4(r0.z, r0.w, r1.x, r1.y);
            ewv = r1.z;
        }
        *reinterpret_cast<float4*>(&s_tile[w][lane][32]) = ea;
        s_d[w][lane] = di;
        s_ew[w][lane] = ewv;

        // cooperative gather: 8-lane groups, 4 edges per iteration
        const int g = lane >> 3;       // group 0..3
        const int j = lane & 7;        // float4 index within row
#pragma unroll
        for (int i = 0; i < 8; i++) {
            const int t = i * 4 + g;
            const int ss = __shfl_sync(0xffffffffu, si, t);
            const int dd = __shfl_sync(0xffffffffu, di, t);
            const float4 a = pb[ss * 8 + j];
            const float4 b = pb[dd * 8 + j];
            *reinterpret_cast<float4*>(&s_tile[w][t][j * 4]) =
                make_float4(a.x - b.x, a.y - b.y, a.z - b.z, a.w - b.w);
        }
        __syncwarp();

        // per-edge compute, lane = channel
        for (int t = 0; t < 32; t++) {
            const float m = s_tile[w][t][lane];
            const float4 e4 = *reinterpret_cast<const float4*>(&s_tile[w][t][32]);
            float h = m + b1c;
            h = fmaf(e4.x, w1b.x, h);
            h = fmaf(e4.y, w1b.y, h);
            h = fmaf(e4.z, w1b.z, h);
            h = fmaf(e4.w, w1b.w, h);
            h = fmaxf(h, 0.0f);
            s_tile[w][t][lane] = h;
            __syncwarp();

            float f = b2c;
#pragma unroll
            for (int jj = 0; jj < 8; jj++) {
                const float4 h4 =
                    *reinterpret_cast<const float4*>(&s_tile[w][t][jj * 4]);
                f = fmaf(h4.x, w2r[4 * jj + 0], f);
                f = fmaf(h4.y, w2r[4 * jj + 1], f);
                f = fmaf(h4.z, w2r[4 * jj + 2], f);
                f = fmaf(h4.w, w2r[4 * jj + 3], f);
            }
            f = fmaxf(f, 0.0f) * s_ew[w][t];

            float* dst = g_acc + (size_t)s_d[w][t] * CO + lane;
            asm volatile("red.global.add.f32 [%0], %1;"
                         :: "l"(dst), "f"(f) : "memory");
        }
        __syncwarp();
    }
}

// ---------------------------------------------------------------------------
// Kernel 4: out = acc / max(cnt,1) + skip      (pure streaming, float4)
// ---------------------------------------------------------------------------
__global__ void __launch_bounds__(256) k_finalize(float* __restrict__ out, int N)
{
    const int i = blockIdx.x * blockDim.x + threadIdx.x;   // over N*8 float4s
    if (i >= N * 8) return;
    const int n = i >> 3;
    const float inv = 1.0f / fmaxf((float)g_cnt[n], 1.0f);
    const float4 a = reinterpret_cast<const float4*>(g_acc)[i];
    const float4 s = reinterpret_cast<const float4*>(g_skip)[i];
    float4 o;
    o.x = fmaf(a.x, inv, s.x);
    o.y = fmaf(a.y, inv, s.y);
    o.z = fmaf(a.z, inv, s.z);
    o.w = fmaf(a.w, inv, s.w);
    reinterpret_cast<float4*>(out)[i] = o;
}

// ---------------------------------------------------------------------------
// Host launcher
// ---------------------------------------------------------------------------
extern "C" void kernel_launch(void* const* d_in, const int* in_sizes, int n_in,
                              void* d_out, int out_size)
{
    const float* x    = (const float*)d_in[0];   // [N, 32]
    const float* pos  = (const float*)d_in[1];   // [N, 2]
    const int*   ei   = (const int*)  d_in[2];   // [2, E]
    const float* ea   = (const float*)d_in[3];   // [E, 4]
    const float* ew   = (const float*)d_in[4];   // [E]
    const float* W1   = (const float*)d_in[5];   // [8, 36, 32]
    const float* b1   = (const float*)d_in[6];   // [8, 32]
    const float* W2   = (const float*)d_in[7];   // [8, 32, 32]
    const float* b2   = (const float*)d_in[8];   // [8, 32]
    const float* Wr   = (const float*)d_in[9];   // [32, 32]
    const float* br   = (const float*)d_in[10];  // [32]
    float* out = (float*)d_out;

    const int N = in_sizes[0] / CI;
    const int E = in_sizes[4];

    // 0) zero scratch
    k_zero<<<512, 256>>>(N);

    // 1) classify: counting sort into 8 branches, packed 32B records
    k_classify<<<(E + 255) / 256, 256>>>(pos, ei, ea, ew, E);

    // 2) per-node precompute: p[k] = x @ W1a[k], skip = x @ Wr + br
    {
        dim3 grid((N + 255) / 256, KB + 1);
        k_precompute<<<grid, 256>>>(x, W1, Wr, br, N);
    }

    // 3) warp-tile edge MLP, branch-specialized blocks
    {
        dim3 grid(64, KB);
        k_edge_mlp<<<grid, 32 * WPB>>>(W1, b1, W2, b2, N);
    }

    // 4) mean + skip connection
    k_finalize<<<(N * 8 + 255) / 256, 256>>>(out, N);
}

// round 6
// speedup vs baseline: 2.0665x; 1.3311x over previous
#include <cuda_runtime.h>
#include <cstdint>

#define NMAX 50000
#define EMAX 800000
#define KB 8          // branches
#define CI 32
#define CO 32
#define CM 36         // C_IN + 4
#define TS 36         // h-tile row stride (floats); 144B keeps 16B alignment

// scratch (device globals; allocation is forbidden)
__device__ float  g_acc[NMAX * CO];            // per-node accumulated edge features
__device__ float  g_skip[NMAX * CO];           // x @ Wr + br
__device__ float  g_p[KB * NMAX * CO];         // per-branch x @ W1a  (51.2 MB)
__device__ int    g_cnt[NMAX];                 // in-degree
__device__ float4 g_bucket[KB * EMAX * 2];     // 32B records {s,d,ea4,ew}
__device__ int    g_bcnt[KB];

// ---------------------------------------------------------------------------
// helpers: tf32 convert + mma
// ---------------------------------------------------------------------------
__device__ __forceinline__ uint32_t f2tf32(float x) {
    uint32_t r;
    asm("cvt.rna.tf32.f32 %0, %1;" : "=r"(r) : "f"(x));
    return r;
}
__device__ __forceinline__ void mma_tf32(float c[4], const uint32_t a[4],
                                         uint32_t b0, uint32_t b1) {
    asm volatile(
        "mma.sync.aligned.m16n8k8.row.col.f32.tf32.tf32.f32 "
        "{%0,%1,%2,%3}, {%4,%5,%6,%7}, {%8,%9}, {%0,%1,%2,%3};"
        : "+f"(c[0]), "+f"(c[1]), "+f"(c[2]), "+f"(c[3])
        : "r"(a[0]), "r"(a[1]), "r"(a[2]), "r"(a[3]), "r"(b0), "r"(b1));
}

// ---------------------------------------------------------------------------
// Kernel 0: zero accumulators / counters
// ---------------------------------------------------------------------------
__global__ void k_zero(int N) {
    int i = blockIdx.x * blockDim.x + threadIdx.x;
    int stride = gridDim.x * blockDim.x;
    float4* a4 = reinterpret_cast<float4*>(g_acc);
    const int n4 = N * CO / 4;
    for (int j = i; j < n4; j += stride) a4[j] = make_float4(0.f, 0.f, 0.f, 0.f);
    for (int j = i; j < N; j += stride) g_cnt[j] = 0;
    if (i < KB) g_bcnt[i] = 0;
}

// ---------------------------------------------------------------------------
// Kernel 1: classify edges into 8 branches (block-aggregated counting sort),
// emit packed 32B records {s, d, ea4, ew}, count in-degree.
// ---------------------------------------------------------------------------
__global__ void __launch_bounds__(256) k_classify(
    const float* __restrict__ pos,
    const int* __restrict__ ei,
    const float* __restrict__ ea,
    const float* __restrict__ ew,
    int E)
{
    __shared__ int s_cnt[KB];
    __shared__ int s_base[KB];
    int t = threadIdx.x;
    if (t < KB) s_cnt[t] = 0;
    __syncthreads();

    int e = blockIdx.x * blockDim.x + t;
    int k = 0, r = 0, s = 0, d = 0;
    float4 a4 = make_float4(0.f, 0.f, 0.f, 0.f);
    float w = 0.f;
    if (e < E) {
        s = ei[e];
        d = ei[E + e];
        a4 = reinterpret_cast<const float4*>(ea)[e];
        w = ew[e];
        float2 ps = reinterpret_cast<const float2*>(pos)[s];
        float2 pd = reinterpret_cast<const float2*>(pos)[d];
        float dx = ps.x - pd.x;
        float dy = ps.y - pd.y;
        k = (dx > 0.0f ? 1 : 0) + (dy > 0.0f ? 2 : 0)
          + ((fabsf(dx) - fabsf(dy)) > 0.0f ? 4 : 0);
        r = atomicAdd(&s_cnt[k], 1);
        atomicAdd(&g_cnt[d], 1);
    }
    __syncthreads();
    if (t < KB) s_base[t] = atomicAdd(&g_bcnt[t], s_cnt[t]);
    __syncthreads();
    if (e < E) {
        size_t p = (size_t)(k * EMAX + s_base[k] + r) * 2;
        g_bucket[p]     = make_float4(__int_as_float(s), __int_as_float(d), a4.x, a4.y);
        g_bucket[p + 1] = make_float4(a4.z, a4.w, w, 0.f);
    }
}

// ---------------------------------------------------------------------------
// Kernel 2: precompute p[k] = x @ W1[k][0:32,:]  (k<8)  and  skip = x@Wr + br
// ---------------------------------------------------------------------------
__global__ void __launch_bounds__(256) k_precompute(
    const float* __restrict__ x,
    const float* __restrict__ W1,
    const float* __restrict__ Wr,
    const float* __restrict__ br,
    int N)
{
    const int k = blockIdx.y;              // 0..7 = branches, 8 = skip
    __shared__ float4 s_w[CO * 8];         // s_w[c*8+ii] = W[4ii..4ii+3][c]
    __shared__ float  s_b[CO];

    const float* W = (k < KB) ? (W1 + k * CM * CO) : Wr;
    float* s_wf = reinterpret_cast<float*>(s_w);
    for (int t = threadIdx.x; t < CO * CI; t += blockDim.x) {
        int c = t >> 5, i = t & 31;
        s_wf[c * 32 + i] = W[i * CO + c];
    }
    for (int t = threadIdx.x; t < CO; t += blockDim.x)
        s_b[t] = (k == KB) ? br[t] : 0.0f;
    __syncthreads();

    const int n = blockIdx.x * blockDim.x + threadIdx.x;
    if (n >= N) return;

    float xr[CI];
    const float4* xv = reinterpret_cast<const float4*>(x) + n * 8;
#pragma unroll
    for (int ii = 0; ii < 8; ii++) {
        float4 v = xv[ii];
        xr[4 * ii + 0] = v.x; xr[4 * ii + 1] = v.y;
        xr[4 * ii + 2] = v.z; xr[4 * ii + 3] = v.w;
    }

    float4* outp = reinterpret_cast<float4*>(
        (k < KB) ? (g_p + (size_t)(k * N + n) * CO) : (g_skip + (size_t)n * CO));

    float o[4];
#pragma unroll
    for (int c = 0; c < CO; c++) {
        float acc = s_b[c];
#pragma unroll
        for (int ii = 0; ii < 8; ii++) {
            float4 w = s_w[c * 8 + ii];
            acc = fmaf(xr[4 * ii + 0], w.x, acc);
            acc = fmaf(xr[4 * ii + 1], w.y, acc);
            acc = fmaf(xr[4 * ii + 2], w.z, acc);
            acc = fmaf(xr[4 * ii + 3], w.w, acc);
        }
        o[c & 3] = acc;
        if ((c & 3) == 3)
            outp[c >> 2] = make_float4(o[0], o[1], o[2], o[3]);
    }
}

// ---------------------------------------------------------------------------
// Kernel 3: warp-tile edge MLP with tf32 MMA layer 2.
//   - cooperative gather fuses layer 1 (diff + ea@W1b + b1, relu) -> h tile
//   - layer 2: 32x32x32 GEMM per tile via mma.sync tf32, 3-term hi/lo split
//   - epilogue: relu(c + b2) * ew, red.v2 scatter
// ---------------------------------------------------------------------------
#define WPB 4   // warps per block
__global__ void __launch_bounds__(32 * WPB) k_edge_mlp(
    const float* __restrict__ W1,
    const float* __restrict__ b1,
    const float* __restrict__ W2,
    const float* __restrict__ b2,
    int N)
{
    const int k    = blockIdx.y;
    const int lane = threadIdx.x & 31;
    const int w    = threadIdx.x >> 5;

    __shared__ float  s_h[WPB][32][TS];    // h tile, row stride 36 floats
    __shared__ float4 s_ea[WPB][32];
    __shared__ float2 s_ewd[WPB][32];      // {ew, d_as_float}

    // ---- per-lane layer-1 tail weights: channels cj = (lane&7)*4 .. +3 ----
    const int j = lane & 7;
    float4 w1b[4];
#pragma unroll
    for (int q = 0; q < 4; q++)
        w1b[q] = *reinterpret_cast<const float4*>(
            W1 + ((size_t)k * CM + 32 + q) * CO + j * 4);
    const float4 b1v = *reinterpret_cast<const float4*>(b1 + k * CO + j * 4);

    // ---- B fragments (W2, K x N col-major mapping), hi/lo, resident ----
    uint32_t Bh[4][4][2], Bl[4][4][2];     // [nt][ks][reg]
    {
        const int col = lane >> 2;          // n within 8-tile
        const int row = lane & 3;           // k within 8-tile
        const float* W2k = W2 + (size_t)k * CO * CO;
#pragma unroll
        for (int nt = 0; nt < 4; nt++)
#pragma unroll
            for (int ks = 0; ks < 4; ks++) {
                float v0 = W2k[(ks * 8 + row) * CO + nt * 8 + col];
                float v1 = W2k[(ks * 8 + row + 4) * CO + nt * 8 + col];
                uint32_t h0 = f2tf32(v0), h1 = f2tf32(v1);
                Bh[nt][ks][0] = h0;
                Bh[nt][ks][1] = h1;
                Bl[nt][ks][0] = f2tf32(v0 - __uint_as_float(h0));
                Bl[nt][ks][1] = f2tf32(v1 - __uint_as_float(h1));
            }
    }
    // b2 pairs per nt for this thread's C columns
    float2 b2v[4];
#pragma unroll
    for (int nt = 0; nt < 4; nt++)
        b2v[nt] = *reinterpret_cast<const float2*>(
            b2 + k * CO + nt * 8 + 2 * (lane & 3));

    const int cnt = g_bcnt[k];
    const int ntile = (cnt + 31) >> 5;
    const float4* __restrict__ rec = g_bucket + (size_t)k * EMAX * 2;
    const float4* __restrict__ pb =
        reinterpret_cast<const float4*>(g_p + (size_t)k * N * CO);

    const int gwarp = blockIdx.x * WPB + w;
    const int nwarp = gridDim.x * WPB;

    for (int tile = gwarp; tile < ntile; tile += nwarp) {
        const int idx = (tile << 5) + lane;
        int si = 0, di = 0;
        float ewv = 0.f;
        float4 ea = make_float4(0.f, 0.f, 0.f, 0.f);
        if (idx < cnt) {
            float4 r0 = rec[(size_t)idx * 2];
            float4 r1 = rec[(size_t)idx * 2 + 1];
            si = __float_as_int(r0.x);
            di = __float_as_int(r0.y);
            ea = make_float4(r0.z, r0.w, r1.x, r1.y);
            ewv = r1.z;
        }
        s_ea[w][lane]  = ea;
        s_ewd[w][lane] = make_float2(ewv, __int_as_float(di));
        __syncwarp();

        // ---- cooperative gather + fused layer 1 ----
        const int g = lane >> 3;
#pragma unroll
        for (int i = 0; i < 8; i++) {
            const int t = i * 4 + g;
            const int ss = __shfl_sync(0xffffffffu, si, t);
            const int dd = __shfl_sync(0xffffffffu, di, t);
            const float4 a  = pb[ss * 8 + j];
            const float4 b  = pb[dd * 8 + j];
            const float4 et = s_ea[w][t];
            float4 h4;
            h4.x = fmaf(et.x, w1b[0].x, fmaf(et.y, w1b[1].x,
                   fmaf(et.z, w1b[2].x, fmaf(et.w, w1b[3].x, b1v.x + a.x - b.x))));
            h4.y = fmaf(et.x, w1b[0].y, fmaf(et.y, w1b[1].y,
                   fmaf(et.z, w1b[2].y, fmaf(et.w, w1b[3].y, b1v.y + a.y - b.y))));
            h4.z = fmaf(et.x, w1b[0].z, fmaf(et.y, w1b[1].z,
                   fmaf(et.z, w1b[2].z, fmaf(et.w, w1b[3].z, b1v.z + a.z - b.z))));
            h4.w = fmaf(et.x, w1b[0].w, fmaf(et.y, w1b[1].w,
                   fmaf(et.z, w1b[2].w, fmaf(et.w, w1b[3].w, b1v.w + a.w - b.w))));
            h4.x = fmaxf(h4.x, 0.f);
            h4.y = fmaxf(h4.y, 0.f);
            h4.z = fmaxf(h4.z, 0.f);
            h4.w = fmaxf(h4.w, 0.f);
            *reinterpret_cast<float4*>(&s_h[w][t][j * 4]) = h4;
        }
        __syncwarp();

        // ---- layer 2: tf32 MMA, 2 M-tiles x 4 N-tiles x 4 K-steps ----
#pragma unroll
        for (int mt = 0; mt < 2; mt++) {
            const int ra = mt * 16 + (lane >> 2);
            const int rb = ra + 8;
            uint32_t Ah[4][4], Al[4][4];
#pragma unroll
            for (int ks = 0; ks < 4; ks++) {
                const int ca = ks * 8 + (lane & 3);
                const float a0 = s_h[w][ra][ca];
                const float a1 = s_h[w][rb][ca];
                const float a2 = s_h[w][ra][ca + 4];
                const float a3 = s_h[w][rb][ca + 4];
                Ah[ks][0] = f2tf32(a0); Al[ks][0] = f2tf32(a0 - __uint_as_float(Ah[ks][0]));
                Ah[ks][1] = f2tf32(a1); Al[ks][1] = f2tf32(a1 - __uint_as_float(Ah[ks][1]));
                Ah[ks][2] = f2tf32(a2); Al[ks][2] = f2tf32(a2 - __uint_as_float(Ah[ks][2]));
                Ah[ks][3] = f2tf32(a3); Al[ks][3] = f2tf32(a3 - __uint_as_float(Ah[ks][3]));
            }
            const float2 ewd_a = s_ewd[w][ra];
            const float2 ewd_b = s_ewd[w][rb];
            float* dst_a = g_acc + (size_t)__float_as_int(ewd_a.y) * CO + 2 * (lane & 3);
            float* dst_b = g_acc + (size_t)__float_as_int(ewd_b.y) * CO + 2 * (lane & 3);
#pragma unroll
            for (int nt = 0; nt < 4; nt++) {
                float c[4] = {0.f, 0.f, 0.f, 0.f};
#pragma unroll
                for (int ks = 0; ks < 4; ks++) {
                    mma_tf32(c, Ah[ks], Bh[nt][ks][0], Bh[nt][ks][1]);
                    mma_tf32(c, Al[ks], Bh[nt][ks][0], Bh[nt][ks][1]);
                    mma_tf32(c, Ah[ks], Bl[nt][ks][0], Bl[nt][ks][1]);
                }
                const float f0 = fmaxf(c[0] + b2v[nt].x, 0.f) * ewd_a.x;
                const float f1 = fmaxf(c[1] + b2v[nt].y, 0.f) * ewd_a.x;
                const float f2 = fmaxf(c[2] + b2v[nt].x, 0.f) * ewd_b.x;
                const float f3 = fmaxf(c[3] + b2v[nt].y, 0.f) * ewd_b.x;
                asm volatile("red.global.add.v2.f32 [%0], {%1, %2};"
                             :: "l"(dst_a + nt * 8), "f"(f0), "f"(f1) : "memory");
                asm volatile("red.global.add.v2.f32 [%0], {%1, %2};"
                             :: "l"(dst_b + nt * 8), "f"(f2), "f"(f3) : "memory");
            }
        }
        __syncwarp();
    }
}

// ---------------------------------------------------------------------------
// Kernel 4: out = acc / max(cnt,1) + skip      (pure streaming, float4)
// ---------------------------------------------------------------------------
__global__ void __launch_bounds__(256) k_finalize(float* __restrict__ out, int N)
{
    const int i = blockIdx.x * blockDim.x + threadIdx.x;   // over N*8 float4s
    if (i >= N * 8) return;
    const int n = i >> 3;
    const float inv = 1.0f / fmaxf((float)g_cnt[n], 1.0f);
    const float4 a = reinterpret_cast<const float4*>(g_acc)[i];
    const float4 s = reinterpret_cast<const float4*>(g_skip)[i];
    float4 o;
    o.x = fmaf(a.x, inv, s.x);
    o.y = fmaf(a.y, inv, s.y);
    o.z = fmaf(a.z, inv, s.z);
    o.w = fmaf(a.w, inv, s.w);
    reinterpret_cast<float4*>(out)[i] = o;
}

// ---------------------------------------------------------------------------
// Host launcher
// ---------------------------------------------------------------------------
extern "C" void kernel_launch(void* const* d_in, const int* in_sizes, int n_in,
                              void* d_out, int out_size)
{
    const float* x    = (const float*)d_in[0];   // [N, 32]
    const float* pos  = (const float*)d_in[1];   // [N, 2]
    const int*   ei   = (const int*)  d_in[2];   // [2, E]
    const float* ea   = (const float*)d_in[3];   // [E, 4]
    const float* ew   = (const float*)d_in[4];   // [E]
    const float* W1   = (const float*)d_in[5];   // [8, 36, 32]
    const float* b1   = (const float*)d_in[6];   // [8, 32]
    const float* W2   = (const float*)d_in[7];   // [8, 32, 32]
    const float* b2   = (const float*)d_in[8];   // [8, 32]
    const float* Wr   = (const float*)d_in[9];   // [32, 32]
    const float* br   = (const float*)d_in[10];  // [32]
    float* out = (float*)d_out;

    const int N = in_sizes[0] / CI;
    const int E = in_sizes[4];

    // 0) zero scratch
    k_zero<<<512, 256>>>(N);

    // 1) classify: counting sort into 8 branches, packed 32B records
    k_classify<<<(E + 255) / 256, 256>>>(pos, ei, ea, ew, E);

    // 2) per-node precompute: p[k] = x @ W1a[k], skip = x @ Wr + br
    {
        dim3 grid((N + 255) / 256, KB + 1);
        k_precompute<<<grid, 256>>>(x, W1, Wr, br, N);
    }

    // 3) warp-tile edge MLP with tensor-core layer 2
    {
        dim3 grid(128, KB);
        k_edge_mlp<<<grid, 32 * WPB>>>(W1, b1, W2, b2, N);
    }

    // 4) mean + skip connection
    k_finalize<<<(N * 8 + 255) / 256, 256>>>(out, N);
}

// round 7
// speedup vs baseline: 2.3692x; 1.1465x over previous
#include <cuda_runtime.h>
#include <cstdint>

#define NMAX 50000
#define EMAX 800000
#define KB 8          // branches
#define CI 32
#define CO 32
#define CM 36         // C_IN + 4
#define TS 36         // h-tile row stride (floats)

// scratch (device globals; allocation is forbidden)
__device__ float  g_acc[NMAX * CO];          // per-node accumulated edge features
__device__ float  g_skip[NMAX * CO];         // x @ Wr + br
__device__ float  g_p[KB * NMAX * CO];       // per-branch x @ W1a
__device__ int    g_cnt[NMAX];               // in-degree
__device__ int2   g_sd[KB * EMAX];           // {src, dst} per branch slot
__device__ float4 g_eab[KB * EMAX];          // edge_attr per branch slot
__device__ float  g_ewb[KB * EMAX];          // edge_weight per branch slot
__device__ int    g_bcnt[KB];

// ---------------------------------------------------------------------------
// helpers: bf16 hi/lo split + bf16 mma
// ---------------------------------------------------------------------------
__device__ __forceinline__ void split2(float x0, float x1,
                                       uint32_t& hi, uint32_t& lo) {
    uint32_t h;
    asm("cvt.rn.bf16x2.f32 %0, %1, %2;" : "=r"(h) : "f"(x1), "f"(x0)); // lo=x0
    const float h0 = __uint_as_float(h << 16);
    const float h1 = __uint_as_float(h & 0xffff0000u);
    const float l0 = x0 - h0;
    const float l1 = x1 - h1;
    uint32_t l;
    asm("cvt.rn.bf16x2.f32 %0, %1, %2;" : "=r"(l) : "f"(l1), "f"(l0));
    hi = h; lo = l;
}
__device__ __forceinline__ void mma_bf16(float c[4], const uint32_t a[4],
                                         const uint32_t b[2]) {
    asm volatile(
        "mma.sync.aligned.m16n8k16.row.col.f32.bf16.bf16.f32 "
        "{%0,%1,%2,%3}, {%4,%5,%6,%7}, {%8,%9}, {%0,%1,%2,%3};"
        : "+f"(c[0]), "+f"(c[1]), "+f"(c[2]), "+f"(c[3])
        : "r"(a[0]), "r"(a[1]), "r"(a[2]), "r"(a[3]), "r"(b[0]), "r"(b[1]));
}

// ---------------------------------------------------------------------------
// Kernel 0 (tiny): zero per-node counters + bucket counts
// ---------------------------------------------------------------------------
__global__ void k_zero_cnt(int N) {
    int i = blockIdx.x * blockDim.x + threadIdx.x;
    int stride = gridDim.x * blockDim.x;
    for (int j = i; j < N; j += stride) g_cnt[j] = 0;
    if (i < KB) g_bcnt[i] = 0;
}

// ---------------------------------------------------------------------------
// Kernel 1: classify edges into 8 branches (block-aggregated counting sort),
// SoA outputs {sd, ea, ew}; count in-degree.
// ---------------------------------------------------------------------------
__global__ void __launch_bounds__(256) k_classify(
    const float* __restrict__ pos,
    const int* __restrict__ ei,
    const float* __restrict__ ea,
    const float* __restrict__ ew,
    int E)
{
    __shared__ int s_cnt[KB];
    __shared__ int s_base[KB];
    int t = threadIdx.x;
    if (t < KB) s_cnt[t] = 0;
    __syncthreads();

    int e = blockIdx.x * blockDim.x + t;
    int k = 0, r = 0, s = 0, d = 0;
    float4 a4 = make_float4(0.f, 0.f, 0.f, 0.f);
    float w = 0.f;
    if (e < E) {
        s = ei[e];
        d = ei[E + e];
        a4 = reinterpret_cast<const float4*>(ea)[e];
        w = ew[e];
        float2 ps = reinterpret_cast<const float2*>(pos)[s];
        float2 pd = reinterpret_cast<const float2*>(pos)[d];
        float dx = ps.x - pd.x;
        float dy = ps.y - pd.y;
        k = (dx > 0.0f ? 1 : 0) + (dy > 0.0f ? 2 : 0)
          + ((fabsf(dx) - fabsf(dy)) > 0.0f ? 4 : 0);
        r = atomicAdd(&s_cnt[k], 1);
        atomicAdd(&g_cnt[d], 1);
    }
    __syncthreads();
    if (t < KB) s_base[t] = atomicAdd(&g_bcnt[t], s_cnt[t]);
    __syncthreads();
    if (e < E) {
        const int slot = k * EMAX + s_base[k] + r;
        g_sd[slot]  = make_int2(s, d);
        g_eab[slot] = a4;
        g_ewb[slot] = w;
    }
}

// ---------------------------------------------------------------------------
// Kernel 2: precompute p[k] = x @ W1[k][0:32,:] (k<8), skip = x@Wr+br (k=8),
// zero g_acc (k=9).
// ---------------------------------------------------------------------------
__global__ void __launch_bounds__(256) k_precompute(
    const float* __restrict__ x,
    const float* __restrict__ W1,
    const float* __restrict__ Wr,
    const float* __restrict__ br,
    int N)
{
    const int k = blockIdx.y;              // 0..7 branches, 8 skip, 9 zero
    if (k == KB + 1) {
        float4* a4 = reinterpret_cast<float4*>(g_acc);
        const int n4 = N * CO / 4;
        const int stride = gridDim.x * blockDim.x;
        for (int j = blockIdx.x * blockDim.x + threadIdx.x; j < n4; j += stride)
            a4[j] = make_float4(0.f, 0.f, 0.f, 0.f);
        return;
    }

    __shared__ float4 s_w[CO * 8];         // s_w[c*8+ii] = W[4ii..4ii+3][c]
    __shared__ float  s_b[CO];

    const float* W = (k < KB) ? (W1 + k * CM * CO) : Wr;
    float* s_wf = reinterpret_cast<float*>(s_w);
    for (int t = threadIdx.x; t < CO * CI; t += blockDim.x) {
        int c = t >> 5, i = t & 31;
        s_wf[c * 32 + i] = W[i * CO + c];
    }
    for (int t = threadIdx.x; t < CO; t += blockDim.x)
        s_b[t] = (k == KB) ? br[t] : 0.0f;
    __syncthreads();

    const int n = blockIdx.x * blockDim.x + threadIdx.x;
    if (n >= N) return;

    float xr[CI];
    const float4* xv = reinterpret_cast<const float4*>(x) + n * 8;
#pragma unroll
    for (int ii = 0; ii < 8; ii++) {
        float4 v = xv[ii];
        xr[4 * ii + 0] = v.x; xr[4 * ii + 1] = v.y;
        xr[4 * ii + 2] = v.z; xr[4 * ii + 3] = v.w;
    }

    float4* outp = reinterpret_cast<float4*>(
        (k < KB) ? (g_p + (size_t)(k * N + n) * CO) : (g_skip + (size_t)n * CO));

    float o[4];
#pragma unroll
    for (int c = 0; c < CO; c++) {
        float acc = s_b[c];
#pragma unroll
        for (int ii = 0; ii < 8; ii++) {
            float4 w = s_w[c * 8 + ii];
            acc = fmaf(xr[4 * ii + 0], w.x, acc);
            acc = fmaf(xr[4 * ii + 1], w.y, acc);
            acc = fmaf(xr[4 * ii + 2], w.z, acc);
            acc = fmaf(xr[4 * ii + 3], w.w, acc);
        }
        o[c & 3] = acc;
        if ((c & 3) == 3)
            outp[c >> 2] = make_float4(o[0], o[1], o[2], o[3]);
    }
}

// ---------------------------------------------------------------------------
// Kernel 3: warp-tile edge MLP.
//   gather + fused layer 1 -> h tile (fp32 in smem)
//   layer 2: bf16 mma m16n8k16, 2-term hi/lo split (3 products)
//   epilogue: relu(c+b2)*ew -> smem transpose -> red.v4 coalesced scatter
// ---------------------------------------------------------------------------
#define WPB 4   // warps per block
__global__ void __launch_bounds__(32 * WPB, 4) k_edge_mlp(
    const float* __restrict__ W1,
    const float* __restrict__ b1,
    const float* __restrict__ W2,
    const float* __restrict__ b2,
    int N)
{
    const int k    = blockIdx.y;
    const int lane = threadIdx.x & 31;
    const int w    = threadIdx.x >> 5;

    __shared__ float  s_h[WPB][32][TS];    // h tile / C transpose buffer
    __shared__ float4 s_ea[WPB][32];
    __shared__ float  s_ew[WPB][32];
    __shared__ int    s_d[WPB][32];

    // ---- per-lane layer-1 tail weights (channels j*4..j*4+3) ----
    const int j = lane & 7;
    float4 w1b[4];
#pragma unroll
    for (int q = 0; q < 4; q++)
        w1b[q] = *reinterpret_cast<const float4*>(
            W1 + ((size_t)k * CM + 32 + q) * CO + j * 4);
    const float4 b1v = *reinterpret_cast<const float4*>(b1 + k * CO + j * 4);

    // ---- B fragments (W2), bf16 hi/lo, resident: Bh/Bl[nt][ks][2] ----
    uint32_t Bh[4][2][2], Bl[4][2][2];
    {
        const int col = lane >> 2;
        const int r2  = (lane & 3) * 2;
        const float* W2k = W2 + (size_t)k * CO * CO;
#pragma unroll
        for (int nt = 0; nt < 4; nt++)
#pragma unroll
            for (int ks = 0; ks < 2; ks++) {
                const int r0 = ks * 16 + r2;
                split2(W2k[(r0    ) * CO + nt * 8 + col],
                       W2k[(r0 + 1) * CO + nt * 8 + col],
                       Bh[nt][ks][0], Bl[nt][ks][0]);
                split2(W2k[(r0 + 8) * CO + nt * 8 + col],
                       W2k[(r0 + 9) * CO + nt * 8 + col],
                       Bh[nt][ks][1], Bl[nt][ks][1]);
            }
    }
    float2 b2v[4];
#pragma unroll
    for (int nt = 0; nt < 4; nt++)
        b2v[nt] = *reinterpret_cast<const float2*>(
            b2 + k * CO + nt * 8 + 2 * (lane & 3));

    const int cnt = g_bcnt[k];
    const int ntile = (cnt + 31) >> 5;
    const int2*   __restrict__ sd = g_sd  + (size_t)k * EMAX;
    const float4* __restrict__ eab = g_eab + (size_t)k * EMAX;
    const float*  __restrict__ ewb = g_ewb + (size_t)k * EMAX;
    const float4* __restrict__ pb =
        reinterpret_cast<const float4*>(g_p + (size_t)k * N * CO);

    const int gwarp = blockIdx.x * WPB + w;
    const int nwarp = gridDim.x * WPB;

    for (int tile = gwarp; tile < ntile; tile += nwarp) {
        const int idx = (tile << 5) + lane;
        int si = 0, di = 0;
        float ewv = 0.f;
        float4 ea = make_float4(0.f, 0.f, 0.f, 0.f);
        if (idx < cnt) {
            int2 p = sd[idx];
            si = p.x; di = p.y;
            ea = eab[idx];
            ewv = ewb[idx];
        }
        s_ea[w][lane] = ea;
        s_ew[w][lane] = ewv;
        s_d[w][lane]  = di;
        __syncwarp();

        // ---- cooperative gather + fused layer 1 ----
        const int g = lane >> 3;
#pragma unroll
        for (int i = 0; i < 8; i++) {
            const int t = i * 4 + g;
            const int ss = __shfl_sync(0xffffffffu, si, t);
            const int dd = __shfl_sync(0xffffffffu, di, t);
            const float4 a  = pb[ss * 8 + j];
            const float4 b  = pb[dd * 8 + j];
            const float4 et = s_ea[w][t];
            float4 h4;
            h4.x = fmaf(et.x, w1b[0].x, fmaf(et.y, w1b[1].x,
                   fmaf(et.z, w1b[2].x, fmaf(et.w, w1b[3].x, b1v.x + a.x - b.x))));
            h4.y = fmaf(et.x, w1b[0].y, fmaf(et.y, w1b[1].y,
                   fmaf(et.z, w1b[2].y, fmaf(et.w, w1b[3].y, b1v.y + a.y - b.y))));
            h4.z = fmaf(et.x, w1b[0].z, fmaf(et.y, w1b[1].z,
                   fmaf(et.z, w1b[2].z, fmaf(et.w, w1b[3].z, b1v.z + a.z - b.z))));
            h4.w = fmaf(et.x, w1b[0].w, fmaf(et.y, w1b[1].w,
                   fmaf(et.z, w1b[2].w, fmaf(et.w, w1b[3].w, b1v.w + a.w - b.w))));
            h4.x = fmaxf(h4.x, 0.f);
            h4.y = fmaxf(h4.y, 0.f);
            h4.z = fmaxf(h4.z, 0.f);
            h4.w = fmaxf(h4.w, 0.f);
            *reinterpret_cast<float4*>(&s_h[w][t][j * 4]) = h4;
        }
        __syncwarp();

        // ---- layer 2: bf16 MMA (2 mt x 4 nt x 2 ks x 3 terms) ----
#pragma unroll
        for (int mt = 0; mt < 2; mt++) {
            const int ra = mt * 16 + (lane >> 2);
            const int rb = ra + 8;
            const int c2 = (lane & 3) * 2;
            uint32_t Ah[2][4], Al[2][4];
#pragma unroll
            for (int ks = 0; ks < 2; ks++) {
                const int k0 = ks * 16 + c2;
                float2 v0 = *reinterpret_cast<const float2*>(&s_h[w][ra][k0]);
                float2 v1 = *reinterpret_cast<const float2*>(&s_h[w][rb][k0]);
                float2 v2 = *reinterpret_cast<const float2*>(&s_h[w][ra][k0 + 8]);
                float2 v3 = *reinterpret_cast<const float2*>(&s_h[w][rb][k0 + 8]);
                split2(v0.x, v0.y, Ah[ks][0], Al[ks][0]);
                split2(v1.x, v1.y, Ah[ks][1], Al[ks][1]);
                split2(v2.x, v2.y, Ah[ks][2], Al[ks][2]);
                split2(v3.x, v3.y, Ah[ks][3], Al[ks][3]);
            }
            const float ewa = s_ew[w][ra];
            const float ewb2 = s_ew[w][rb];
#pragma unroll
            for (int nt = 0; nt < 4; nt++) {
                float c[4] = {0.f, 0.f, 0.f, 0.f};
#pragma unroll
                for (int ks = 0; ks < 2; ks++) {
                    mma_bf16(c, Ah[ks], Bh[nt][ks]);
                    mma_bf16(c, Al[ks], Bh[nt][ks]);
                    mma_bf16(c, Ah[ks], Bl[nt][ks]);
                }
                float2 fa, fb;
                fa.x = fmaxf(c[0] + b2v[nt].x, 0.f) * ewa;
                fa.y = fmaxf(c[1] + b2v[nt].y, 0.f) * ewa;
                fb.x = fmaxf(c[2] + b2v[nt].x, 0.f) * ewb2;
                fb.y = fmaxf(c[3] + b2v[nt].y, 0.f) * ewb2;
                *reinterpret_cast<float2*>(&s_h[w][ra][nt * 8 + c2]) = fa;
                *reinterpret_cast<float2*>(&s_h[w][rb][nt * 8 + c2]) = fb;
            }
        }
        __syncwarp();

        // ---- coalesced scatter: one full edge row per 8 lanes, red.v4 ----
        const int c4 = (lane & 7) * 4;
#pragma unroll
        for (int i = 0; i < 8; i++) {
            const int r = i * 4 + (lane >> 3);
            const float4 v = *reinterpret_cast<const float4*>(&s_h[w][r][c4]);
            float* dst = g_acc + (size_t)s_d[w][r] * CO + c4;
            asm volatile("red.global.add.v4.f32 [%0], {%1, %2, %3, %4};"
                         :: "l"(dst), "f"(v.x), "f"(v.y), "f"(v.z), "f"(v.w)
                         : "memory");
        }
        __syncwarp();
    }
}

// ---------------------------------------------------------------------------
// Kernel 4: out = acc / max(cnt,1) + skip      (pure streaming, float4)
// ---------------------------------------------------------------------------
__global__ void __launch_bounds__(256) k_finalize(float* __restrict__ out, int N)
{
    const int i = blockIdx.x * blockDim.x + threadIdx.x;   // over N*8 float4s
    if (i >= N * 8) return;
    const int n = i >> 3;
    const float inv = 1.0f / fmaxf((float)g_cnt[n], 1.0f);
    const float4 a = reinterpret_cast<const float4*>(g_acc)[i];
    const float4 s = reinterpret_cast<const float4*>(g_skip)[i];
    float4 o;
    o.x = fmaf(a.x, inv, s.x);
    o.y = fmaf(a.y, inv, s.y);
    o.z = fmaf(a.z, inv, s.z);
    o.w = fmaf(a.w, inv, s.w);
    reinterpret_cast<float4*>(out)[i] = o;
}

// ---------------------------------------------------------------------------
// Host launcher
// ---------------------------------------------------------------------------
extern "C" void kernel_launch(void* const* d_in, const int* in_sizes, int n_in,
                              void* d_out, int out_size)
{
    const float* x    = (const float*)d_in[0];   // [N, 32]
    const float* pos  = (const float*)d_in[1];   // [N, 2]
    const int*   ei   = (const int*)  d_in[2];   // [2, E]
    const float* ea   = (const float*)d_in[3];   // [E, 4]
    const float* ew   = (const float*)d_in[4];   // [E]
    const float* W1   = (const float*)d_in[5];   // [8, 36, 32]
    const float* b1   = (const float*)d_in[6];   // [8, 32]
    const float* W2   = (const float*)d_in[7];   // [8, 32, 32]
    const float* b2   = (const float*)d_in[8];   // [8, 32]
    const float* Wr   = (const float*)d_in[9];   // [32, 32]
    const float* br   = (const float*)d_in[10];  // [32]
    float* out = (float*)d_out;

    const int N = in_sizes[0] / CI;
    const int E = in_sizes[4];

    // 0) zero counters (small)
    k_zero_cnt<<<64, 256>>>(N);

    // 1) classify: counting sort into 8 branches, SoA records
    k_classify<<<(E + 255) / 256, 256>>>(pos, ei, ea, ew, E);

    // 2) per-node precompute + g_acc zero (grid.y: 8 branches + skip + zero)
    {
        dim3 grid((N + 255) / 256, KB + 2);
        k_precompute<<<grid, 256>>>(x, W1, Wr, br, N);
    }

    // 3) warp-tile edge MLP (bf16 tensor-core layer 2)
    {
        dim3 grid(128, KB);
        k_edge_mlp<<<grid, 32 * WPB>>>(W1, b1, W2, b2, N);
    }

    // 4) mean + skip connection
    k_finalize<<<(N * 8 + 255) / 256, 256>>>(out, N);
}

// round 8
// speedup vs baseline: 3.3123x; 1.3981x over previous
#include <cuda_runtime.h>
#include <cstdint>

#define NMAX 50000
#define EMAX 800000
#define KB 8          // branches
#define CI 32
#define CO 32
#define CM 36         // C_IN + 4
#define TS 36         // h-tile row stride (floats)
#define PNT 36        // precompute n-tiles: 8 branches*4 + skip*4

// scratch (device globals; allocation is forbidden)
__device__ float    g_acc[NMAX * CO];        // per-node accumulated edge features
__device__ float    g_skip[NMAX * CO];       // x @ Wr (br folded into finalize)
__device__ float    g_p[KB * NMAX * CO];     // per-branch x @ W1a
__device__ int      g_cnt[NMAX];             // in-degree
__device__ uint32_t g_sdp[KB * EMAX];        // packed {s:16, d:16} per branch slot
__device__ float4   g_eab[KB * EMAX];        // edge_attr per branch slot
__device__ float    g_ewb[KB * EMAX];        // edge_weight per branch slot
__device__ int      g_bcnt[KB];

// ---------------------------------------------------------------------------
// helpers: bf16 hi/lo split + bf16 mma
// ---------------------------------------------------------------------------
__device__ __forceinline__ void split2(float x0, float x1,
                                       uint32_t& hi, uint32_t& lo) {
    uint32_t h;
    asm("cvt.rn.bf16x2.f32 %0, %1, %2;" : "=r"(h) : "f"(x1), "f"(x0)); // lo=x0
    const float h0 = __uint_as_float(h << 16);
    const float h1 = __uint_as_float(h & 0xffff0000u);
    const float l0 = x0 - h0;
    const float l1 = x1 - h1;
    uint32_t l;
    asm("cvt.rn.bf16x2.f32 %0, %1, %2;" : "=r"(l) : "f"(l1), "f"(l0));
    hi = h; lo = l;
}
__device__ __forceinline__ void mma_bf16(float c[4], const uint32_t a[4],
                                         const uint32_t b[2]) {
    asm volatile(
        "mma.sync.aligned.m16n8k16.row.col.f32.bf16.bf16.f32 "
        "{%0,%1,%2,%3}, {%4,%5,%6,%7}, {%8,%9}, {%0,%1,%2,%3};"
        : "+f"(c[0]), "+f"(c[1]), "+f"(c[2]), "+f"(c[3])
        : "r"(a[0]), "r"(a[1]), "r"(a[2]), "r"(a[3]), "r"(b[0]), "r"(b[1]));
}

// ---------------------------------------------------------------------------
// Kernel 0: zero g_acc + per-node counters + bucket counts
// ---------------------------------------------------------------------------
__global__ void k_zero(int N) {
    int i = blockIdx.x * blockDim.x + threadIdx.x;
    int stride = gridDim.x * blockDim.x;
    float4* a4 = reinterpret_cast<float4*>(g_acc);
    const int n4 = N * CO / 4;
    for (int j = i; j < n4; j += stride) a4[j] = make_float4(0.f, 0.f, 0.f, 0.f);
    for (int j = i; j < N; j += stride) g_cnt[j] = 0;
    if (i < KB) g_bcnt[i] = 0;
}

// ---------------------------------------------------------------------------
// Kernel 1: classify edges into 8 branches (block-aggregated counting sort),
// SoA outputs {sd packed, ea, ew}; count in-degree.
// ---------------------------------------------------------------------------
__global__ void __launch_bounds__(256) k_classify(
    const float* __restrict__ pos,
    const int* __restrict__ ei,
    const float* __restrict__ ea,
    const float* __restrict__ ew,
    int E)
{
    __shared__ int s_cnt[KB];
    __shared__ int s_base[KB];
    int t = threadIdx.x;
    if (t < KB) s_cnt[t] = 0;
    __syncthreads();

    int e = blockIdx.x * blockDim.x + t;
    int k = 0, r = 0, s = 0, d = 0;
    float4 a4 = make_float4(0.f, 0.f, 0.f, 0.f);
    float w = 0.f;
    if (e < E) {
        s = ei[e];
        d = ei[E + e];
        a4 = reinterpret_cast<const float4*>(ea)[e];
        w = ew[e];
        float2 ps = reinterpret_cast<const float2*>(pos)[s];
        float2 pd = reinterpret_cast<const float2*>(pos)[d];
        float dx = ps.x - pd.x;
        float dy = ps.y - pd.y;
        k = (dx > 0.0f ? 1 : 0) + (dy > 0.0f ? 2 : 0)
          + ((fabsf(dx) - fabsf(dy)) > 0.0f ? 4 : 0);
        r = atomicAdd(&s_cnt[k], 1);
        atomicAdd(&g_cnt[d], 1);
    }
    __syncthreads();
    if (t < KB) s_base[t] = atomicAdd(&g_bcnt[t], s_cnt[t]);
    __syncthreads();
    if (e < E) {
        const int slot = k * EMAX + s_base[k] + r;
        g_sdp[slot] = ((uint32_t)s << 16) | (uint32_t)d;
        g_eab[slot] = a4;
        g_ewb[slot] = w;
    }
}

// ---------------------------------------------------------------------------
// Kernel 2: tensor-core precompute: [p0..p7 | skip] = x @ [W1a_0..W1a_7 | Wr]
// One warp = 32-node tile; B fragments (bf16 hi/lo) prebuilt in SMEM.
// ---------------------------------------------------------------------------
__global__ void __launch_bounds__(256) k_precompute_mma(
    const float* __restrict__ x,
    const float* __restrict__ W1,
    const float* __restrict__ Wr,
    int N)
{
    __shared__ uint32_t s_B[PNT * 2 * 32 * 4];   // 36 KB

    // build B fragments: col-major m16n8k16 B frags, hi/lo split
    for (int idx = threadIdx.x; idx < PNT * 2 * 32; idx += blockDim.x) {
        const int lane = idx & 31, ks = (idx >> 5) & 1, nt = idx >> 6;
        const int cg = lane >> 2, r2 = (lane & 3) * 2;
        const float* src;
        if (nt < 32) src = W1 + ((size_t)(nt >> 2) * CM) * CO + (nt & 3) * 8 + cg;
        else         src = Wr + (nt - 32) * 8 + cg;
        const int r0 = ks * 16 + r2;
        uint32_t h0, l0, h1, l1;
        split2(src[(r0    ) * CO], src[(r0 + 1) * CO], h0, l0);
        split2(src[(r0 + 8) * CO], src[(r0 + 9) * CO], h1, l1);
        uint32_t* dst = &s_B[idx * 4];
        dst[0] = h0; dst[1] = h1; dst[2] = l0; dst[3] = l1;
    }
    __syncthreads();

    const int lane = threadIdx.x & 31;
    const int gid = lane >> 2, tig = lane & 3;
    const int wid = blockIdx.x * (blockDim.x >> 5) + (threadIdx.x >> 5);
    const int nwarp = gridDim.x * (blockDim.x >> 5);
    const int ntile = (N + 31) >> 5;

    for (int tile = wid; tile < ntile; tile += nwarp) {
        const int n0 = (tile << 5) + gid;

        // A fragments from x rows (row-major), hi/lo split
        uint32_t Ah[2][2][4], Al[2][2][4];
#pragma unroll
        for (int mt = 0; mt < 2; mt++) {
            const int na = min(n0 + mt * 16, N - 1);
            const int nb = min(n0 + mt * 16 + 8, N - 1);
#pragma unroll
            for (int ks = 0; ks < 2; ks++) {
                const int c0 = ks * 16 + tig * 2;
                float2 v0 = *reinterpret_cast<const float2*>(x + (size_t)na * CI + c0);
                float2 v1 = *reinterpret_cast<const float2*>(x + (size_t)nb * CI + c0);
                float2 v2 = *reinterpret_cast<const float2*>(x + (size_t)na * CI + c0 + 8);
                float2 v3 = *reinterpret_cast<const float2*>(x + (size_t)nb * CI + c0 + 8);
                split2(v0.x, v0.y, Ah[mt][ks][0], Al[mt][ks][0]);
                split2(v1.x, v1.y, Ah[mt][ks][1], Al[mt][ks][1]);
                split2(v2.x, v2.y, Ah[mt][ks][2], Al[mt][ks][2]);
                split2(v3.x, v3.y, Ah[mt][ks][3], Al[mt][ks][3]);
            }
        }

#pragma unroll
        for (int nt = 0; nt < PNT; nt++) {
            float c[2][4] = {{0.f,0.f,0.f,0.f},{0.f,0.f,0.f,0.f}};
#pragma unroll
            for (int ks = 0; ks < 2; ks++) {
                const uint4 bq = *reinterpret_cast<const uint4*>(
                    &s_B[((nt * 2 + ks) * 32 + lane) * 4]);
                uint32_t bh[2] = {bq.x, bq.y};
                uint32_t bl[2] = {bq.z, bq.w};
#pragma unroll
                for (int mt = 0; mt < 2; mt++) {
                    mma_bf16(c[mt], Ah[mt][ks], bh);
                    mma_bf16(c[mt], Al[mt][ks], bh);
                    mma_bf16(c[mt], Ah[mt][ks], bl);
                }
            }
            float* base;
            int ch;
            if (nt < 32) { base = g_p + (size_t)(nt >> 2) * N * CO; ch = (nt & 3) * 8 + tig * 2; }
            else         { base = g_skip;                            ch = (nt - 32) * 8 + tig * 2; }
#pragma unroll
            for (int mt = 0; mt < 2; mt++) {
                const int na = n0 + mt * 16;
                if (na < N)
                    *reinterpret_cast<float2*>(base + (size_t)na * CO + ch) =
                        make_float2(c[mt][0], c[mt][1]);
                if (na + 8 < N)
                    *reinterpret_cast<float2*>(base + (size_t)(na + 8) * CO + ch) =
                        make_float2(c[mt][2], c[mt][3]);
            }
        }
    }
}

// ---------------------------------------------------------------------------
// Kernel 3: warp-tile edge MLP.
//   gather + fused layer 1 -> h tile (fp32 in smem)
//   layer 2: bf16 mma m16n8k16, 2-term hi/lo split (3 products)
//   epilogue: relu(c+b2)*ew -> smem transpose -> red.v4 coalesced scatter
// ---------------------------------------------------------------------------
#define WPB 4   // warps per block
__global__ void __launch_bounds__(32 * WPB, 4) k_edge_mlp(
    const float* __restrict__ W1,
    const float* __restrict__ b1,
    const float* __restrict__ W2,
    const float* __restrict__ b2,
    int N)
{
    const int k    = blockIdx.y;
    const int lane = threadIdx.x & 31;
    const int w    = threadIdx.x >> 5;

    __shared__ float  s_h[WPB][32][TS];    // h tile / C transpose buffer
    __shared__ float4 s_ea[WPB][32];
    __shared__ float  s_ew[WPB][32];
    __shared__ int    s_d[WPB][32];

    // ---- per-lane layer-1 tail weights (channels j*4..j*4+3) ----
    const int j = lane & 7;
    float4 w1b[4];
#pragma unroll
    for (int q = 0; q < 4; q++)
        w1b[q] = *reinterpret_cast<const float4*>(
            W1 + ((size_t)k * CM + 32 + q) * CO + j * 4);
    const float4 b1v = *reinterpret_cast<const float4*>(b1 + k * CO + j * 4);

    // ---- B fragments (W2), bf16 hi/lo, resident ----
    uint32_t Bh[4][2][2], Bl[4][2][2];
    {
        const int col = lane >> 2;
        const int r2  = (lane & 3) * 2;
        const float* W2k = W2 + (size_t)k * CO * CO;
#pragma unroll
        for (int nt = 0; nt < 4; nt++)
#pragma unroll
            for (int ks = 0; ks < 2; ks++) {
                const int r0 = ks * 16 + r2;
                split2(W2k[(r0    ) * CO + nt * 8 + col],
                       W2k[(r0 + 1) * CO + nt * 8 + col],
                       Bh[nt][ks][0], Bl[nt][ks][0]);
                split2(W2k[(r0 + 8) * CO + nt * 8 + col],
                       W2k[(r0 + 9) * CO + nt * 8 + col],
                       Bh[nt][ks][1], Bl[nt][ks][1]);
            }
    }
    float2 b2v[4];
#pragma unroll
    for (int nt = 0; nt < 4; nt++)
        b2v[nt] = *reinterpret_cast<const float2*>(
            b2 + k * CO + nt * 8 + 2 * (lane & 3));

    const int cnt = g_bcnt[k];
    const int ntile = (cnt + 31) >> 5;
    const uint32_t* __restrict__ sdp = g_sdp + (size_t)k * EMAX;
    const float4*   __restrict__ eab = g_eab + (size_t)k * EMAX;
    const float*    __restrict__ ewb = g_ewb + (size_t)k * EMAX;
    const float4*   __restrict__ pb =
        reinterpret_cast<const float4*>(g_p + (size_t)k * N * CO);

    const int gwarp = blockIdx.x * WPB + w;
    const int nwarp = gridDim.x * WPB;

    for (int tile = gwarp; tile < ntile; tile += nwarp) {
        const int idx = (tile << 5) + lane;
        int si = 0, di = 0;
        float ewv = 0.f;
        float4 ea = make_float4(0.f, 0.f, 0.f, 0.f);
        if (idx < cnt) {
            const uint32_t p = sdp[idx];
            si = (int)(p >> 16);
            di = (int)(p & 0xffffu);
            ea = eab[idx];
            ewv = ewb[idx];
        }
        s_ea[w][lane] = ea;
        s_ew[w][lane] = ewv;
        s_d[w][lane]  = di;
        __syncwarp();

        // ---- cooperative gather + fused layer 1 ----
        const int g = lane >> 3;
#pragma unroll
        for (int i = 0; i < 8; i++) {
            const int t = i * 4 + g;
            const int ss = __shfl_sync(0xffffffffu, si, t);
            const int dd = __shfl_sync(0xffffffffu, di, t);
            const float4 a  = pb[ss * 8 + j];
            const float4 b  = pb[dd * 8 + j];
            const float4 et = s_ea[w][t];
            float4 h4;
            h4.x = fmaf(et.x, w1b[0].x, fmaf(et.y, w1b[1].x,
                   fmaf(et.z, w1b[2].x, fmaf(et.w, w1b[3].x, b1v.x + a.x - b.x))));
            h4.y = fmaf(et.x, w1b[0].y, fmaf(et.y, w1b[1].y,
                   fmaf(et.z, w1b[2].y, fmaf(et.w, w1b[3].y, b1v.y + a.y - b.y))));
            h4.z = fmaf(et.x, w1b[0].z, fmaf(et.y, w1b[1].z,
                   fmaf(et.z, w1b[2].z, fmaf(et.w, w1b[3].z, b1v.z + a.z - b.z))));
            h4.w = fmaf(et.x, w1b[0].w, fmaf(et.y, w1b[1].w,
                   fmaf(et.z, w1b[2].w, fmaf(et.w, w1b[3].w, b1v.w + a.w - b.w))));
            h4.x = fmaxf(h4.x, 0.f);
            h4.y = fmaxf(h4.y, 0.f);
            h4.z = fmaxf(h4.z, 0.f);
            h4.w = fmaxf(h4.w, 0.f);
            *reinterpret_cast<float4*>(&s_h[w][t][j * 4]) = h4;
        }
        __syncwarp();

        // ---- layer 2: bf16 MMA (2 mt x 4 nt x 2 ks x 3 terms) ----
#pragma unroll
        for (int mt = 0; mt < 2; mt++) {
            const int ra = mt * 16 + (lane >> 2);
            const int rb = ra + 8;
            const int c2 = (lane & 3) * 2;
            uint32_t Ah[2][4], Al[2][4];
#pragma unroll
            for (int ks = 0; ks < 2; ks++) {
                const int k0 = ks * 16 + c2;
                float2 v0 = *reinterpret_cast<const float2*>(&s_h[w][ra][k0]);
                float2 v1 = *reinterpret_cast<const float2*>(&s_h[w][rb][k0]);
                float2 v2 = *reinterpret_cast<const float2*>(&s_h[w][ra][k0 + 8]);
                float2 v3 = *reinterpret_cast<const float2*>(&s_h[w][rb][k0 + 8]);
                split2(v0.x, v0.y, Ah[ks][0], Al[ks][0]);
                split2(v1.x, v1.y, Ah[ks][1], Al[ks][1]);
                split2(v2.x, v2.y, Ah[ks][2], Al[ks][2]);
                split2(v3.x, v3.y, Ah[ks][3], Al[ks][3]);
            }
            const float ewa = s_ew[w][ra];
            const float ewb2 = s_ew[w][rb];
#pragma unroll
            for (int nt = 0; nt < 4; nt++) {
                float c[4] = {0.f, 0.f, 0.f, 0.f};
#pragma unroll
                for (int ks = 0; ks < 2; ks++) {
                    mma_bf16(c, Ah[ks], Bh[nt][ks]);
                    mma_bf16(c, Al[ks], Bh[nt][ks]);
                    mma_bf16(c, Ah[ks], Bl[nt][ks]);
                }
                float2 fa, fb;
                fa.x = fmaxf(c[0] + b2v[nt].x, 0.f) * ewa;
                fa.y = fmaxf(c[1] + b2v[nt].y, 0.f) * ewa;
                fb.x = fmaxf(c[2] + b2v[nt].x, 0.f) * ewb2;
                fb.y = fmaxf(c[3] + b2v[nt].y, 0.f) * ewb2;
                *reinterpret_cast<float2*>(&s_h[w][ra][nt * 8 + c2]) = fa;
                *reinterpret_cast<float2*>(&s_h[w][rb][nt * 8 + c2]) = fb;
            }
        }
        __syncwarp();

        // ---- coalesced scatter: one full edge row per 8 lanes, red.v4 ----
        const int c4 = (lane & 7) * 4;
#pragma unroll
        for (int i = 0; i < 8; i++) {
            const int r = i * 4 + (lane >> 3);
            const float4 v = *reinterpret_cast<const float4*>(&s_h[w][r][c4]);
            float* dst = g_acc + (size_t)s_d[w][r] * CO + c4;
            asm volatile("red.global.add.v4.f32 [%0], {%1, %2, %3, %4};"
                         :: "l"(dst), "f"(v.x), "f"(v.y), "f"(v.z), "f"(v.w)
                         : "memory");
        }
        __syncwarp();
    }
}

// ---------------------------------------------------------------------------
// Kernel 4: out = acc / max(cnt,1) + skip + br   (pure streaming, float4)
// ---------------------------------------------------------------------------
__global__ void __launch_bounds__(256) k_finalize(
    float* __restrict__ out, const float* __restrict__ br, int N)
{
    const int i = blockIdx.x * blockDim.x + threadIdx.x;   // over N*8 float4s
    if (i >= N * 8) return;
    const int n = i >> 3;
    const float inv = 1.0f / fmaxf((float)g_cnt[n], 1.0f);
    const float4 a = reinterpret_cast<const float4*>(g_acc)[i];
    const float4 s = reinterpret_cast<const float4*>(g_skip)[i];
    const float4 b = reinterpret_cast<const float4*>(br)[i & 7];
    float4 o;
    o.x = fmaf(a.x, inv, s.x + b.x);
    o.y = fmaf(a.y, inv, s.y + b.y);
    o.z = fmaf(a.z, inv, s.z + b.z);
    o.w = fmaf(a.w, inv, s.w + b.w);
    reinterpret_cast<float4*>(out)[i] = o;
}

// ---------------------------------------------------------------------------
// Host launcher
// ---------------------------------------------------------------------------
extern "C" void kernel_launch(void* const* d_in, const int* in_sizes, int n_in,
                              void* d_out, int out_size)
{
    const float* x    = (const float*)d_in[0];   // [N, 32]
    const float* pos  = (const float*)d_in[1];   // [N, 2]
    const int*   ei   = (const int*)  d_in[2];   // [2, E]
    const float* ea   = (const float*)d_in[3];   // [E, 4]
    const float* ew   = (const float*)d_in[4];   // [E]
    const float* W1   = (const float*)d_in[5];   // [8, 36, 32]
    const float* b1   = (const float*)d_in[6];   // [8, 32]
    const float* W2   = (const float*)d_in[7];   // [8, 32, 32]
    const float* b2   = (const float*)d_in[8];   // [8, 32]
    const float* Wr   = (const float*)d_in[9];   // [32, 32]
    const float* br   = (const float*)d_in[10];  // [32]
    float* out = (float*)d_out;

    const int N = in_sizes[0] / CI;
    const int E = in_sizes[4];

    // 0) zero scratch
    k_zero<<<256, 256>>>(N);

    // 1) classify: counting sort into 8 branches, SoA records
    k_classify<<<(E + 255) / 256, 256>>>(pos, ei, ea, ew, E);

    // 2) tensor-core precompute: p[0..7] and skip in one GEMM
    {
        const int ntile = (N + 31) / 32;
        const int blocks = (ntile + 7) / 8;    // 8 warps per block
        k_precompute_mma<<<blocks, 256>>>(x, W1, Wr, N);
    }

    // 3) warp-tile edge MLP (bf16 tensor-core layer 2)
    {
        dim3 grid(128, KB);
        k_edge_mlp<<<grid, 32 * WPB>>>(W1, b1, W2, b2, N);
    }

    // 4) mean + skip connection (+ br)
    k_finalize<<<(N * 8 + 255) / 256, 256>>>(out, br, N);
}